// round 13
// baseline (speedup 1.0000x reference)
#include <cuda_runtime.h>
#include <cuda_fp16.h>
#include <cstdint>

// ---------------------------------------------------------------------------
// SO3_Linear: out[b,m,o] = sum_i x[b,m,i] * W[l(m)][o][i]  (+ bias on m==0)
// B=20000, M=49, IN=OUT=128, LMAX=6 (7 weights)
//
// sm_103 BASE target: warp-level mma.sync.m16n8k16 f16 with fp32 accum.
// fp16 TWO-term compensation:  acc = Xh*Wh + Xl*Wh   (= (xh+xl)*wh)
// Software-pipelined tile loop: double-buffered X smem, one sync per tile,
// next tile's X global loads issued into registers during current MMA.
// 4 warps/CTA (warp tile 32x64), 2 CTAs/SM, NTILE=8 tiles per CTA.
// ---------------------------------------------------------------------------

#define B_TOTAL   20000
#define M_TOTAL   49
#define IN_DIM    128
#define OUT_DIM   128
#define TB        64                              // batch rows per tile
#define NXTILES   ((B_TOTAL + TB - 1) / TB)       // 313
#define NTILE     8                               // b-tiles per CTA
#define NB_CTAS   ((NXTILES + NTILE - 1) / NTILE) // 40
#define NTHREADS  128

#define PITCH     136                             // fp16 elems per smem row (272 B)
#define XBUF_SZ   (TB * PITCH * 2)                // 17408 B (one XH or XL buffer)

// SMEM byte offsets: XH0, XL0, XH1, XL1, WH
#define SMEM_X    0
#define SMEM_WH   (4 * XBUF_SZ)                   // 69632
#define SMEM_TOTAL (SMEM_WH + OUT_DIM * PITCH * 2) // 104448

__device__ __forceinline__ uint32_t smem_u32(const void* p) {
    uint32_t a;
    asm("{ .reg .u64 t; cvta.to.shared.u64 t, %1; cvt.u32.u64 %0, t; }"
        : "=r"(a) : "l"(p));
    return a;
}

__device__ __forceinline__ uint32_t pack_h2(__half a, __half b) {
    return (uint32_t)__half_as_ushort(a) | ((uint32_t)__half_as_ushort(b) << 16);
}

// Split two fp32 into (hi, lo) fp16x2 pairs: v = hi + lo (+ tiny residual)
__device__ __forceinline__ void split2h(float a, float b, uint32_t& h, uint32_t& l) {
    __half ah = __float2half_rn(a);
    __half bh = __float2half_rn(b);
    float ar = a - __half2float(ah);
    float br = b - __half2float(bh);
    h = pack_h2(ah, bh);
    l = pack_h2(__float2half_rn(ar), __float2half_rn(br));
}

__device__ __forceinline__ uint32_t cvt2h(float a, float b) {
    return pack_h2(__float2half_rn(a), __float2half_rn(b));
}

__device__ __forceinline__ void ldmatrix_x4(uint32_t& r0, uint32_t& r1,
                                            uint32_t& r2, uint32_t& r3,
                                            uint32_t addr) {
    asm volatile("ldmatrix.sync.aligned.m8n8.x4.shared.b16 {%0,%1,%2,%3}, [%4];"
                 : "=r"(r0), "=r"(r1), "=r"(r2), "=r"(r3) : "r"(addr));
}

__device__ __forceinline__ void mma_16816(float* d, const uint32_t* a,
                                          const uint32_t* b) {
    asm volatile(
        "mma.sync.aligned.m16n8k16.row.col.f32.f16.f16.f32 "
        "{%0,%1,%2,%3}, {%4,%5,%6,%7}, {%8,%9}, {%0,%1,%2,%3};"
        : "+f"(d[0]), "+f"(d[1]), "+f"(d[2]), "+f"(d[3])
        : "r"(a[0]), "r"(a[1]), "r"(a[2]), "r"(a[3]), "r"(b[0]), "r"(b[1]));
}

__global__ void __launch_bounds__(NTHREADS, 2)
so3_linear_kernel(const float* __restrict__ x,      // [B, M, IN]
                  const float* __restrict__ w,      // [7, OUT, IN]
                  const float* __restrict__ bias,   // [OUT]
                  float* __restrict__ out)          // [B, M, OUT]
{
    extern __shared__ char smem[];
    const uint32_t sbase = smem_u32(smem);
    const int tid  = threadIdx.x;
    const int wid  = tid >> 5;
    const int lane = tid & 31;

    const int m = (int)blockIdx.y;

    // l(m): largest l with l*l <= m
    int l = 0;
    while ((l + 1) * (l + 1) <= m) ++l;

    // X-load mapping: idx = tid + it*128 -> row = idx>>4, ck = idx&15
    const int xrow = tid >> 4;                        // rows step by 8 per it
    const int xck  = tid & 15;

    // ---- Prefetch tile 0's X into registers ----
    float4 v[8][2];
    {
        const int tile0 = (int)blockIdx.x * NTILE;
        const int b0 = tile0 * TB;
        #pragma unroll
        for (int it = 0; it < 8; it++) {
            int row = xrow + it * 8;
            int b = b0 + row;
            if (b < B_TOTAL) {
                const float4* p =
                    (const float4*)(x + ((size_t)b * M_TOTAL + m) * IN_DIM + xck * 8);
                v[it][0] = p[0]; v[it][1] = p[1];
            } else {
                v[it][0] = make_float4(0.f, 0.f, 0.f, 0.f);
                v[it][1] = v[it][0];
            }
        }
    }

    // ---- Convert W[l] once (128x128 f32 -> fp16 Wh, pitch 136) ----
    {
        const float* wl = w + (size_t)l * OUT_DIM * IN_DIM;
        #pragma unroll
        for (int it = 0; it < 16; it++) {
            int idx = tid + it * NTHREADS;            // 0 .. 2047
            int row = idx >> 4;                       // o (N dim)
            int ck  = idx & 15;                       // 8-float chunk along K
            const float4* p = (const float4*)(wl + (size_t)row * IN_DIM + ck * 8);
            float4 w0 = p[0], w1 = p[1];
            uint4 hv = make_uint4(cvt2h(w0.x, w0.y), cvt2h(w0.z, w0.w),
                                  cvt2h(w1.x, w1.y), cvt2h(w1.z, w1.w));
            uint32_t off = ((uint32_t)row * PITCH + (uint32_t)ck * 8) * 2;
            *(uint4*)(smem + SMEM_WH + off) = hv;
        }
    }

    // ---- Warp tiling: 2 (m) x 2 (n) warps, each owns 32x64 output ----
    const int mrow = (wid >> 1) * 32;                 // 0 or 32
    const int ncol = (wid & 1) * 64;                  // 0 or 64

    // ldmatrix lane->address components
    const int ag = lane >> 3;                         // A: matrix index 0..3
    const int ar = (lane & 7) + ((ag & 1) << 3);      // A: row within 16
    const int ac = (ag >> 1) << 3;                    // A: col 0 or 8
    const int bn = ((lane >> 4) << 3) + (lane & 7);   // B: n-row within 16
    const int bk = ((lane >> 3) & 1) << 3;            // B: k col 0 or 8

    for (int t = 0; t < NTILE; t++) {
        const int tile = (int)blockIdx.x * NTILE + t;
        if (tile >= NXTILES) break;
        const int b0 = tile * TB;

        const uint32_t xh_off = (uint32_t)(t & 1) * (2 * XBUF_SZ);
        const uint32_t xl_off = xh_off + XBUF_SZ;

        // ---- Split prefetched X and store to this tile's buffers ----
        #pragma unroll
        for (int it = 0; it < 8; it++) {
            uint32_t h[4], lo[4];
            split2h(v[it][0].x, v[it][0].y, h[0], lo[0]);
            split2h(v[it][0].z, v[it][0].w, h[1], lo[1]);
            split2h(v[it][1].x, v[it][1].y, h[2], lo[2]);
            split2h(v[it][1].z, v[it][1].w, h[3], lo[3]);
            uint32_t off = ((uint32_t)(xrow + it * 8) * PITCH +
                            (uint32_t)xck * 8) * 2;
            *(uint4*)(smem + SMEM_X + xh_off + off) = make_uint4(h[0], h[1], h[2], h[3]);
            *(uint4*)(smem + SMEM_X + xl_off + off) = make_uint4(lo[0], lo[1], lo[2], lo[3]);
        }
        __syncthreads();   // buffers (and W on first tile) visible to all warps

        // ---- Issue next tile's X loads (drain under the MMA below) ----
        if (t + 1 < NTILE && tile + 1 < NXTILES) {
            const int nb0 = (tile + 1) * TB;
            #pragma unroll
            for (int it = 0; it < 8; it++) {
                int b = nb0 + xrow + it * 8;
                if (b < B_TOTAL) {
                    const float4* p =
                        (const float4*)(x + ((size_t)b * M_TOTAL + m) * IN_DIM + xck * 8);
                    v[it][0] = p[0]; v[it][1] = p[1];
                } else {
                    v[it][0] = make_float4(0.f, 0.f, 0.f, 0.f);
                    v[it][1] = v[it][0];
                }
            }
        }

        // ---- Fused 2-term MMA loop: acc = Xh*Wh + Xl*Wh ----
        float acc[2][8][4];
        #pragma unroll
        for (int mt = 0; mt < 2; mt++)
            #pragma unroll
            for (int nt = 0; nt < 8; nt++)
                #pragma unroll
                for (int i = 0; i < 4; i++) acc[mt][nt][i] = 0.f;

        #pragma unroll
        for (int k = 0; k < 8; k++) {
            const int k0 = k * 16;
            uint32_t ah[2][4], al[2][4], bh[8][2];

            #pragma unroll
            for (int mt = 0; mt < 2; mt++) {
                uint32_t aoff = (((uint32_t)(mrow + mt * 16 + ar)) * PITCH +
                                 (uint32_t)(k0 + ac)) * 2;
                ldmatrix_x4(ah[mt][0], ah[mt][1], ah[mt][2], ah[mt][3],
                            sbase + SMEM_X + xh_off + aoff);
                ldmatrix_x4(al[mt][0], al[mt][1], al[mt][2], al[mt][3],
                            sbase + SMEM_X + xl_off + aoff);
            }
            #pragma unroll
            for (int np = 0; np < 4; np++) {
                uint32_t boff = (((uint32_t)(ncol + np * 16 + bn)) * PITCH +
                                 (uint32_t)(k0 + bk)) * 2;
                uint32_t r0, r1, r2, r3;
                ldmatrix_x4(r0, r1, r2, r3, sbase + SMEM_WH + boff);
                bh[2 * np][0] = r0;     bh[2 * np][1] = r1;
                bh[2 * np + 1][0] = r2; bh[2 * np + 1][1] = r3;
            }

            #pragma unroll
            for (int mt = 0; mt < 2; mt++)
                #pragma unroll
                for (int nt = 0; nt < 8; nt++)
                    mma_16816(acc[mt][nt], ah[mt], bh[nt]);
            #pragma unroll
            for (int mt = 0; mt < 2; mt++)
                #pragma unroll
                for (int nt = 0; nt < 8; nt++)
                    mma_16816(acc[mt][nt], al[mt], bh[nt]);
        }

        // ---- Epilogue: write accumulators to global (+bias on m==0) ----
        {
            const int r  = lane >> 2;                 // 0..7
            const int c2 = (lane & 3) * 2;            // 0,2,4,6
            #pragma unroll
            for (int mt = 0; mt < 2; mt++) {
                #pragma unroll
                for (int half = 0; half < 2; half++) {  // rows r and r+8
                    int row = mrow + mt * 16 + r + half * 8;
                    int b = b0 + row;
                    if (b >= B_TOTAL) continue;
                    float* orow = out + ((size_t)b * M_TOTAL + m) * OUT_DIM;
                    #pragma unroll
                    for (int nt = 0; nt < 8; nt++) {
                        int col = ncol + nt * 8 + c2;
                        float v0 = acc[mt][nt][half * 2 + 0];
                        float v1 = acc[mt][nt][half * 2 + 1];
                        if (m == 0) {
                            v0 += bias[col];
                            v1 += bias[col + 1];
                        }
                        *(float2*)(orow + col) = make_float2(v0, v1);
                    }
                }
            }
        }
    }
}

extern "C" void kernel_launch(void* const* d_in, const int* in_sizes, int n_in,
                              void* d_out, int out_size) {
    const float* x    = (const float*)d_in[0];   // [20000, 49, 128] f32
    const float* w    = (const float*)d_in[1];   // [7, 128, 128] f32
    const float* bias = (const float*)d_in[2];   // [128] f32
    // d_in[3] = expand_index (int64) — l(m) computed in-kernel instead.
    float* out = (float*)d_out;

    cudaFuncSetAttribute(so3_linear_kernel,
                         cudaFuncAttributeMaxDynamicSharedMemorySize, SMEM_TOTAL);

    dim3 grid(NB_CTAS, M_TOTAL);
    so3_linear_kernel<<<grid, NTHREADS, SMEM_TOTAL>>>(x, w, bias, out);
}

// round 15
// speedup vs baseline: 1.2997x; 1.2997x over previous
#include <cuda_runtime.h>
#include <cuda_fp16.h>
#include <cstdint>

// ---------------------------------------------------------------------------
// SO3_Linear: out[b,m,o] = sum_i x[b,m,i] * W[l(m)][o][i]  (+ bias on m==0)
// B=20000, M=49, IN=OUT=128, LMAX=6 (7 weights)
//
// sm_103 BASE target: warp-level mma.sync.m16n8k16 f16, fp32 accum.
// SINGLE-PASS fp16: out = fp16(x) * fp16(w). Dropped terms xl*wh + xh*wl
// give rel L2 err ~2.8e-4 (measured 2-term = 2.17e-4), under 1e-3 gate.
// 4 warps/CTA (warp tile 32x64), CTA tile 64x128, 4 CTAs/SM, NTILE=8.
// ---------------------------------------------------------------------------

#define B_TOTAL   20000
#define M_TOTAL   49
#define IN_DIM    128
#define OUT_DIM   128
#define TB        64                              // batch rows per tile
#define NXTILES   ((B_TOTAL + TB - 1) / TB)       // 313
#define NTILE     8                               // b-tiles per CTA
#define NB_CTAS   ((NXTILES + NTILE - 1) / NTILE) // 40
#define NTHREADS  128

#define PITCH     136                             // fp16 elems per smem row (272 B)

// SMEM byte offsets (16B aligned)
#define SMEM_XH   0
#define SMEM_WH   (TB * PITCH * 2)                    // 17408
#define SMEM_TOTAL (SMEM_WH + OUT_DIM * PITCH * 2)    // 52224

__device__ __forceinline__ uint32_t smem_u32(const void* p) {
    uint32_t a;
    asm("{ .reg .u64 t; cvta.to.shared.u64 t, %1; cvt.u32.u64 %0, t; }"
        : "=r"(a) : "l"(p));
    return a;
}

__device__ __forceinline__ uint32_t pack_h2(__half a, __half b) {
    return (uint32_t)__half_as_ushort(a) | ((uint32_t)__half_as_ushort(b) << 16);
}

__device__ __forceinline__ uint32_t cvt2h(float a, float b) {
    return pack_h2(__float2half_rn(a), __float2half_rn(b));
}

__device__ __forceinline__ void ldmatrix_x4(uint32_t& r0, uint32_t& r1,
                                            uint32_t& r2, uint32_t& r3,
                                            uint32_t addr) {
    asm volatile("ldmatrix.sync.aligned.m8n8.x4.shared.b16 {%0,%1,%2,%3}, [%4];"
                 : "=r"(r0), "=r"(r1), "=r"(r2), "=r"(r3) : "r"(addr));
}

__device__ __forceinline__ void mma_16816(float* d, const uint32_t* a,
                                          const uint32_t* b) {
    asm volatile(
        "mma.sync.aligned.m16n8k16.row.col.f32.f16.f16.f32 "
        "{%0,%1,%2,%3}, {%4,%5,%6,%7}, {%8,%9}, {%0,%1,%2,%3};"
        : "+f"(d[0]), "+f"(d[1]), "+f"(d[2]), "+f"(d[3])
        : "r"(a[0]), "r"(a[1]), "r"(a[2]), "r"(a[3]), "r"(b[0]), "r"(b[1]));
}

__global__ void __launch_bounds__(NTHREADS, 4)
so3_linear_kernel(const float* __restrict__ x,      // [B, M, IN]
                  const float* __restrict__ w,      // [7, OUT, IN]
                  const float* __restrict__ bias,   // [OUT]
                  float* __restrict__ out)          // [B, M, OUT]
{
    extern __shared__ char smem[];
    const uint32_t sbase = smem_u32(smem);
    const int tid  = threadIdx.x;
    const int wid  = tid >> 5;
    const int lane = tid & 31;

    const int m = (int)blockIdx.y;

    // l(m): largest l with l*l <= m
    int l = 0;
    while ((l + 1) * (l + 1) <= m) ++l;

    // ---- Convert W[l] once (128x128 f32 -> fp16 Wh, pitch 136) ----
    {
        const float* wl = w + (size_t)l * OUT_DIM * IN_DIM;
        #pragma unroll
        for (int it = 0; it < 16; it++) {
            int idx = tid + it * NTHREADS;            // 0 .. 2047
            int row = idx >> 4;                       // o (N dim)
            int ck  = idx & 15;                       // 8-float chunk along K
            const float4* p = (const float4*)(wl + (size_t)row * IN_DIM + ck * 8);
            float4 w0 = p[0], w1 = p[1];
            uint4 hv = make_uint4(cvt2h(w0.x, w0.y), cvt2h(w0.z, w0.w),
                                  cvt2h(w1.x, w1.y), cvt2h(w1.z, w1.w));
            uint32_t off = ((uint32_t)row * PITCH + (uint32_t)ck * 8) * 2;
            *(uint4*)(smem + SMEM_WH + off) = hv;
        }
    }

    // ---- Warp tiling: 2 (m) x 2 (n) warps, each owns 32x64 output ----
    const int mrow = (wid >> 1) * 32;                 // 0 or 32
    const int ncol = (wid & 1) * 64;                  // 0 or 64

    // ldmatrix lane->address components
    const int ag = lane >> 3;                         // A: matrix index 0..3
    const int ar = (lane & 7) + ((ag & 1) << 3);      // A: row within 16
    const int ac = (ag >> 1) << 3;                    // A: col 0 or 8
    const int bn = ((lane >> 4) << 3) + (lane & 7);   // B: n-row within 16
    const int bk = ((lane >> 3) & 1) << 3;            // B: k col 0 or 8

    for (int t = 0; t < NTILE; t++) {
        const int tile = (int)blockIdx.x * NTILE + t;
        if (tile >= NXTILES) break;
        const int b0 = tile * TB;

        __syncthreads();   // previous tile's MMA reads of X smem complete

        // ---- Load + convert X tile (64 rows x 128, fp16) ----
        #pragma unroll
        for (int it = 0; it < 8; it++) {
            int idx = tid + it * NTHREADS;            // 0 .. 1023
            int row = idx >> 4;
            int ck  = idx & 15;
            int b = b0 + row;
            float4 v0 = make_float4(0.f, 0.f, 0.f, 0.f), v1 = v0;
            if (b < B_TOTAL) {
                const float4* p =
                    (const float4*)(x + ((size_t)b * M_TOTAL + m) * IN_DIM + ck * 8);
                v0 = p[0]; v1 = p[1];
            }
            uint4 hv = make_uint4(cvt2h(v0.x, v0.y), cvt2h(v0.z, v0.w),
                                  cvt2h(v1.x, v1.y), cvt2h(v1.z, v1.w));
            uint32_t off = ((uint32_t)row * PITCH + (uint32_t)ck * 8) * 2;
            *(uint4*)(smem + SMEM_XH + off) = hv;
        }
        __syncthreads();   // X (and W on first tile) visible to all warps

        // ---- Single-pass MMA loop: acc = Xh*Wh ----
        float acc[2][8][4];
        #pragma unroll
        for (int mt = 0; mt < 2; mt++)
            #pragma unroll
            for (int nt = 0; nt < 8; nt++)
                #pragma unroll
                for (int i = 0; i < 4; i++) acc[mt][nt][i] = 0.f;

        #pragma unroll
        for (int k = 0; k < 8; k++) {
            const int k0 = k * 16;
            uint32_t ah[2][4], bh[8][2];

            #pragma unroll
            for (int mt = 0; mt < 2; mt++) {
                uint32_t aoff = (((uint32_t)(mrow + mt * 16 + ar)) * PITCH +
                                 (uint32_t)(k0 + ac)) * 2;
                ldmatrix_x4(ah[mt][0], ah[mt][1], ah[mt][2], ah[mt][3],
                            sbase + SMEM_XH + aoff);
            }
            #pragma unroll
            for (int np = 0; np < 4; np++) {
                uint32_t boff = (((uint32_t)(ncol + np * 16 + bn)) * PITCH +
                                 (uint32_t)(k0 + bk)) * 2;
                uint32_t r0, r1, r2, r3;
                ldmatrix_x4(r0, r1, r2, r3, sbase + SMEM_WH + boff);
                bh[2 * np][0] = r0;     bh[2 * np][1] = r1;
                bh[2 * np + 1][0] = r2; bh[2 * np + 1][1] = r3;
            }

            #pragma unroll
            for (int mt = 0; mt < 2; mt++)
                #pragma unroll
                for (int nt = 0; nt < 8; nt++)
                    mma_16816(acc[mt][nt], ah[mt], bh[nt]);
        }

        // ---- Epilogue: write accumulators to global (+bias on m==0) ----
        {
            const int r  = lane >> 2;                 // 0..7
            const int c2 = (lane & 3) * 2;            // 0,2,4,6
            #pragma unroll
            for (int mt = 0; mt < 2; mt++) {
                #pragma unroll
                for (int half = 0; half < 2; half++) {  // rows r and r+8
                    int row = mrow + mt * 16 + r + half * 8;
                    int b = b0 + row;
                    if (b >= B_TOTAL) continue;
                    float* orow = out + ((size_t)b * M_TOTAL + m) * OUT_DIM;
                    #pragma unroll
                    for (int nt = 0; nt < 8; nt++) {
                        int col = ncol + nt * 8 + c2;
                        float v0 = acc[mt][nt][half * 2 + 0];
                        float v1 = acc[mt][nt][half * 2 + 1];
                        if (m == 0) {
                            v0 += bias[col];
                            v1 += bias[col + 1];
                        }
                        *(float2*)(orow + col) = make_float2(v0, v1);
                    }
                }
            }
        }
    }
}

extern "C" void kernel_launch(void* const* d_in, const int* in_sizes, int n_in,
                              void* d_out, int out_size) {
    const float* x    = (const float*)d_in[0];   // [20000, 49, 128] f32
    const float* w    = (const float*)d_in[1];   // [7, 128, 128] f32
    const float* bias = (const float*)d_in[2];   // [128] f32
    // d_in[3] = expand_index (int64) — l(m) computed in-kernel instead.
    float* out = (float*)d_out;

    cudaFuncSetAttribute(so3_linear_kernel,
                         cudaFuncAttributeMaxDynamicSharedMemorySize, SMEM_TOTAL);

    dim3 grid(NB_CTAS, M_TOTAL);
    so3_linear_kernel<<<grid, NTHREADS, SMEM_TOTAL>>>(x, w, bias, out);
}

// round 16
// speedup vs baseline: 1.3131x; 1.0103x over previous
#include <cuda_runtime.h>
#include <cuda_fp16.h>
#include <cstdint>

// ---------------------------------------------------------------------------
// SO3_Linear: out[b,m,o] = sum_i x[b,m,i] * W[l(m)][o][i]  (+ bias on m==0)
// B=20000, M=49, IN=OUT=128, LMAX=6 (7 weights)
//
// sm_103 BASE target: warp-level mma.sync.m16n8k16 f16, fp32 accum.
// SINGLE-PASS fp16 (rel err ~3e-4, validated in R13).
// W FRAGMENTS HELD IN REGISTERS: each warp loads its 32-n-wide W slice
// directly from global in the mma B-fragment layout, once per CTA
// (64 regs/thread). No W smem, no B ldmatrix, no W convert phase.
// CTA: 256 thr, tile 64x128, warp grid 2m x 4n of 32x32 tiles, 2 CTAs/SM.
// ---------------------------------------------------------------------------

#define B_TOTAL   20000
#define M_TOTAL   49
#define IN_DIM    128
#define OUT_DIM   128
#define TB        64                              // batch rows per tile
#define NXTILES   ((B_TOTAL + TB - 1) / TB)       // 313
#define NTILE     8                               // b-tiles per CTA
#define NB_CTAS   ((NXTILES + NTILE - 1) / NTILE) // 40
#define NTHREADS  256

#define PITCH     136                             // fp16 elems per smem row (272 B)

// SMEM: X tile only
#define SMEM_XH    0
#define SMEM_TOTAL (TB * PITCH * 2)               // 17408 bytes

__device__ __forceinline__ uint32_t smem_u32(const void* p) {
    uint32_t a;
    asm("{ .reg .u64 t; cvta.to.shared.u64 t, %1; cvt.u32.u64 %0, t; }"
        : "=r"(a) : "l"(p));
    return a;
}

__device__ __forceinline__ uint32_t pack_h2(__half a, __half b) {
    return (uint32_t)__half_as_ushort(a) | ((uint32_t)__half_as_ushort(b) << 16);
}

__device__ __forceinline__ uint32_t cvt2h(float a, float b) {
    return pack_h2(__float2half_rn(a), __float2half_rn(b));
}

__device__ __forceinline__ void ldmatrix_x4(uint32_t& r0, uint32_t& r1,
                                            uint32_t& r2, uint32_t& r3,
                                            uint32_t addr) {
    asm volatile("ldmatrix.sync.aligned.m8n8.x4.shared.b16 {%0,%1,%2,%3}, [%4];"
                 : "=r"(r0), "=r"(r1), "=r"(r2), "=r"(r3) : "r"(addr));
}

__device__ __forceinline__ void mma_16816(float* d, const uint32_t* a,
                                          const uint32_t* b) {
    asm volatile(
        "mma.sync.aligned.m16n8k16.row.col.f32.f16.f16.f32 "
        "{%0,%1,%2,%3}, {%4,%5,%6,%7}, {%8,%9}, {%0,%1,%2,%3};"
        : "+f"(d[0]), "+f"(d[1]), "+f"(d[2]), "+f"(d[3])
        : "r"(a[0]), "r"(a[1]), "r"(a[2]), "r"(a[3]), "r"(b[0]), "r"(b[1]));
}

__global__ void __launch_bounds__(NTHREADS, 2)
so3_linear_kernel(const float* __restrict__ x,      // [B, M, IN]
                  const float* __restrict__ w,      // [7, OUT, IN]
                  const float* __restrict__ bias,   // [OUT]
                  float* __restrict__ out)          // [B, M, OUT]
{
    extern __shared__ char smem[];
    const uint32_t sbase = smem_u32(smem);
    const int tid  = threadIdx.x;
    const int wid  = tid >> 5;
    const int lane = tid & 31;

    const int m = (int)blockIdx.y;

    // l(m): largest l with l*l <= m
    int l = 0;
    while ((l + 1) * (l + 1) <= m) ++l;

    // ---- Warp tiling: 2 (m) x 4 (n) warps, each owns 32x32 output ----
    const int mrow = (wid >> 2) * 32;                 // 0 or 32
    const int ncol = (wid & 3) * 32;                  // 0,32,64,96

    // ---- Load W fragments straight from global into registers (once) ----
    // mma.m16n8k16 B-fragment: breg[0] = {W[n][k0], W[n][k0+1]},
    // breg[1] = {W[n][k0+8], W[n][k0+9]}, n = n8 + lane>>2, k0 = ks*16+(lane&3)*2
    uint32_t wreg[4][8][2];
    {
        const float* wl = w + (size_t)l * OUT_DIM * IN_DIM;
        const int nb = ncol + (lane >> 2);
        const int kb = (lane & 3) * 2;
        #pragma unroll
        for (int nt = 0; nt < 4; nt++) {
            const float* wn = wl + (size_t)(nb + nt * 8) * IN_DIM + kb;
            #pragma unroll
            for (int ks = 0; ks < 8; ks++) {
                float2 v0 = *(const float2*)(wn + ks * 16);
                float2 v1 = *(const float2*)(wn + ks * 16 + 8);
                wreg[nt][ks][0] = cvt2h(v0.x, v0.y);
                wreg[nt][ks][1] = cvt2h(v1.x, v1.y);
            }
        }
    }

    // ldmatrix lane->address components (A operand)
    const int ag = lane >> 3;                         // matrix index 0..3
    const int ar = (lane & 7) + ((ag & 1) << 3);      // row within 16
    const int ac = (ag >> 1) << 3;                    // col 0 or 8

    for (int t = 0; t < NTILE; t++) {
        const int tile = (int)blockIdx.x * NTILE + t;
        if (tile >= NXTILES) break;
        const int b0 = tile * TB;

        __syncthreads();   // previous tile's MMA reads of X smem complete

        // ---- Load + convert X tile (64 rows x 128, fp16) ----
        #pragma unroll
        for (int it = 0; it < 4; it++) {
            int idx = tid + it * NTHREADS;            // 0 .. 1023
            int row = idx >> 4;
            int ck  = idx & 15;
            int b = b0 + row;
            float4 v0 = make_float4(0.f, 0.f, 0.f, 0.f), v1 = v0;
            if (b < B_TOTAL) {
                const float4* p =
                    (const float4*)(x + ((size_t)b * M_TOTAL + m) * IN_DIM + ck * 8);
                v0 = p[0]; v1 = p[1];
            }
            uint4 hv = make_uint4(cvt2h(v0.x, v0.y), cvt2h(v0.z, v0.w),
                                  cvt2h(v1.x, v1.y), cvt2h(v1.z, v1.w));
            uint32_t off = ((uint32_t)row * PITCH + (uint32_t)ck * 8) * 2;
            *(uint4*)(smem + SMEM_XH + off) = hv;
        }
        __syncthreads();   // X visible to all warps

        // ---- MMA loop: acc = Xh * Wreg ----
        float acc[2][4][4];
        #pragma unroll
        for (int mt = 0; mt < 2; mt++)
            #pragma unroll
            for (int nt = 0; nt < 4; nt++)
                #pragma unroll
                for (int i = 0; i < 4; i++) acc[mt][nt][i] = 0.f;

        #pragma unroll
        for (int k = 0; k < 8; k++) {
            const int k0 = k * 16;
            uint32_t ah[2][4];
            #pragma unroll
            for (int mt = 0; mt < 2; mt++) {
                uint32_t aoff = (((uint32_t)(mrow + mt * 16 + ar)) * PITCH +
                                 (uint32_t)(k0 + ac)) * 2;
                ldmatrix_x4(ah[mt][0], ah[mt][1], ah[mt][2], ah[mt][3],
                            sbase + SMEM_XH + aoff);
            }
            #pragma unroll
            for (int mt = 0; mt < 2; mt++)
                #pragma unroll
                for (int nt = 0; nt < 4; nt++)
                    mma_16816(acc[mt][nt], ah[mt], wreg[nt][k]);
        }

        // ---- Epilogue: write accumulators to global (+bias on m==0) ----
        {
            const int r  = lane >> 2;                 // 0..7
            const int c2 = (lane & 3) * 2;            // 0,2,4,6
            #pragma unroll
            for (int mt = 0; mt < 2; mt++) {
                #pragma unroll
                for (int half = 0; half < 2; half++) {  // rows r and r+8
                    int row = mrow + mt * 16 + r + half * 8;
                    int b = b0 + row;
                    if (b >= B_TOTAL) continue;
                    float* orow = out + ((size_t)b * M_TOTAL + m) * OUT_DIM;
                    #pragma unroll
                    for (int nt = 0; nt < 4; nt++) {
                        int col = ncol + nt * 8 + c2;
                        float v0 = acc[mt][nt][half * 2 + 0];
                        float v1 = acc[mt][nt][half * 2 + 1];
                        if (m == 0) {
                            v0 += bias[col];
                            v1 += bias[col + 1];
                        }
                        *(float2*)(orow + col) = make_float2(v0, v1);
                    }
                }
            }
        }
    }
}

extern "C" void kernel_launch(void* const* d_in, const int* in_sizes, int n_in,
                              void* d_out, int out_size) {
    const float* x    = (const float*)d_in[0];   // [20000, 49, 128] f32
    const float* w    = (const float*)d_in[1];   // [7, 128, 128] f32
    const float* bias = (const float*)d_in[2];   // [128] f32
    // d_in[3] = expand_index (int64) — l(m) computed in-kernel instead.
    float* out = (float*)d_out;

    cudaFuncSetAttribute(so3_linear_kernel,
                         cudaFuncAttributeMaxDynamicSharedMemorySize, SMEM_TOTAL);

    dim3 grid(NB_CTAS, M_TOTAL);
    so3_linear_kernel<<<grid, NTHREADS, SMEM_TOTAL>>>(x, w, bias, out);
}